// round 4
// baseline (speedup 1.0000x reference)
#include <cuda_runtime.h>

#define KCH 256      // chunks per batch
#define MAXB 256

__device__ float g_P [(size_t)MAXB * KCH * 64]; // 16 MB of 8x8 chunk matrices
__device__ float g_cs[MAXB * KCH];              // per-chunk log-scale
__device__ float g_score[MAXB];                 // per-batch path score

// ---------------------------------------------------------------------------
// Kernel A: path score. One warp per batch; lanes stride over t. Score is a
// plain sum over timesteps (no recurrence), so this is embarrassingly parallel.
// ---------------------------------------------------------------------------
__global__ void __launch_bounds__(256) crf_score_kernel(
    const float* __restrict__ em,
    const int* __restrict__ tags,          // int32 (JAX demotes int64 w/o x64)
    const int* __restrict__ mask,          // bool marshaled as int32
    const float* __restrict__ trans,
    const float* __restrict__ startt,
    const float* __restrict__ endt,
    int B, int T)
{
    int w    = (blockIdx.x * blockDim.x + threadIdx.x) >> 5;
    int lane = threadIdx.x & 31;
    if (w >= B) return;
    const int b = w;
    const unsigned FULL = 0xffffffffu;
    size_t bT = (size_t)b * T;

    float sp  = 0.0f;
    int   cnt = 0;
    for (int t = 1 + lane; t < T; t += 32) {
        int mk = __ldg(&mask[bT + t]);
        if (mk) {
            int tg = __ldg(&tags[bT + t]);
            int pv = __ldg(&tags[bT + t - 1]);
            sp += __ldg(&em[(bT + t) * 8 + tg]) + __ldg(&trans[pv * 8 + tg]);
            cnt++;
        }
    }
    if (lane == 0) cnt += (__ldg(&mask[bT]) != 0) ? 1 : 0;  // include t=0 in mask sum

#pragma unroll
    for (int off = 16; off >= 1; off >>= 1) {
        sp  += __shfl_xor_sync(FULL, sp,  off);
        cnt += __shfl_xor_sync(FULL, cnt, off);
    }

    if (lane == 0) {
        int last_valid = cnt - 1;
        int tag0  = __ldg(&tags[bT]);
        int lastt = __ldg(&tags[bT + last_valid]);
        float score = __ldg(&startt[tag0]) + __ldg(&em[bT * 8 + tag0])
                    + sp + __ldg(&endt[lastt]);
        g_score[b] = score;
    }
}

// ---------------------------------------------------------------------------
// Kernel 1: each thread = (batch, chunk). 8x8 product of per-step matrices
// A_t = M * diag(exp(emit_t)) for masked steps, rescaled every 4 steps.
// ---------------------------------------------------------------------------
__global__ void __launch_bounds__(128) crf_chunk_kernel(
    const float* __restrict__ em,
    const int* __restrict__ mask,
    const float* __restrict__ trans,
    int B, int T, int L)
{
    int gid = blockIdx.x * blockDim.x + threadIdx.x;
    if (gid >= B * KCH) return;
    int b = gid >> 8;          // / KCH
    int k = gid & (KCH - 1);

    float M[8][8];
#pragma unroll
    for (int i = 0; i < 8; i++)
#pragma unroll
        for (int j = 0; j < 8; j++)
            M[i][j] = __expf(__ldg(&trans[i * 8 + j]));

    float P[8][8];
#pragma unroll
    for (int i = 0; i < 8; i++)
#pragma unroll
        for (int j = 0; j < 8; j++)
            P[i][j] = (i == j) ? 1.0f : 0.0f;

    long long t0 = 1 + (long long)k * L;
    long long t1 = t0 + L; if (t1 > T) t1 = T;

    float c = 0.0f;
    size_t baseBT = (size_t)b * T;
    int cnt = 0;

    for (long long t = t0; t < t1; t++) {
        const float4* ep = (const float4*)(em + (baseBT + t) * 8);
        float4 ea = __ldg(ep);
        float4 eb = __ldg(ep + 1);
        float e[8] = {ea.x, ea.y, ea.z, ea.w, eb.x, eb.y, eb.z, eb.w};
        bool mk = (__ldg(&mask[baseBT + t]) != 0);

        if (mk) {
            float ev[8];
#pragma unroll
            for (int j = 0; j < 8; j++) ev[j] = __expf(e[j]);
#pragma unroll
            for (int i = 0; i < 8; i++) {
                float r[8];
#pragma unroll
                for (int j = 0; j < 8; j++) {
                    float acc = P[i][0] * M[0][j];
#pragma unroll
                    for (int kk = 1; kk < 8; kk++)
                        acc = fmaf(P[i][kk], M[kk][j], acc);
                    r[j] = acc * ev[j];
                }
#pragma unroll
                for (int j = 0; j < 8; j++) P[i][j] = r[j];
            }
        }

        if ((++cnt & 3) == 0) {
            float s = P[0][0] + P[0][1] + P[0][2] + P[0][3]
                    + P[0][4] + P[0][5] + P[0][6] + P[0][7];
            float r = __fdividef(1.0f, s);
            c += __logf(s);
#pragma unroll
            for (int i = 0; i < 8; i++)
#pragma unroll
                for (int j = 0; j < 8; j++) P[i][j] *= r;
        }
    }
    {
        float s = P[0][0] + P[0][1] + P[0][2] + P[0][3]
                + P[0][4] + P[0][5] + P[0][6] + P[0][7];
        float r = __fdividef(1.0f, s);
        c += __logf(s);
#pragma unroll
        for (int i = 0; i < 8; i++)
#pragma unroll
            for (int j = 0; j < 8; j++) P[i][j] *= r;
    }

    float* dst = &g_P[(size_t)gid * 64];
#pragma unroll
    for (int i = 0; i < 8; i++) {
        ((float4*)dst)[i * 2 + 0] = make_float4(P[i][0], P[i][1], P[i][2], P[i][3]);
        ((float4*)dst)[i * 2 + 1] = make_float4(P[i][4], P[i][5], P[i][6], P[i][7]);
    }
    g_cs[gid] = c;
}

// ---------------------------------------------------------------------------
// Kernel B: finalize. One thread per batch. Plain sequential fold: alpha0
// through 256 chunk matrices, rescale per chunk.
// ---------------------------------------------------------------------------
__global__ void crf_finalize_kernel(
    const float* __restrict__ em,
    const float* __restrict__ startt,
    const float* __restrict__ endt,
    float* __restrict__ out,
    int B, int T)
{
    int b = blockIdx.x;
    if (threadIdx.x != 0 || b >= B) return;

    size_t bT = (size_t)b * T;
    float a[8];
#pragma unroll
    for (int j = 0; j < 8; j++)
        a[j] = __expf(__ldg(&startt[j]) + __ldg(&em[bT * 8 + j]));

    const float* Pb  = &g_P [(size_t)b * KCH * 64];
    const float* csb = &g_cs[(size_t)b * KCH];

    float c = 0.0f;
    for (int k = 0; k < KCH; k++) {
        float m[64];
#pragma unroll
        for (int q = 0; q < 16; q++)
            ((float4*)m)[q] = __ldg(((const float4*)(Pb + (size_t)k * 64)) + q);

        float r[8];
#pragma unroll
        for (int j = 0; j < 8; j++) {
            float acc = a[0] * m[0 * 8 + j];
#pragma unroll
            for (int i = 1; i < 8; i++)
                acc = fmaf(a[i], m[i * 8 + j], acc);
            r[j] = acc;
        }
        float s = r[0] + r[1] + r[2] + r[3] + r[4] + r[5] + r[6] + r[7];
        float inv = __fdividef(1.0f, s);
        c += __logf(s) + __ldg(&csb[k]);
#pragma unroll
        for (int j = 0; j < 8; j++) a[j] = r[j] * inv;
    }

    float v = 0.0f;
#pragma unroll
    for (int j = 0; j < 8; j++)
        v += a[j] * __expf(__ldg(&endt[j]));
    float logZ = __logf(v) + c;

    out[b] = logZ - g_score[b];
}

// ---------------------------------------------------------------------------
extern "C" void kernel_launch(void* const* d_in, const int* in_sizes, int n_in,
                              void* d_out, int out_size)
{
    const float* em     = (const float*)d_in[0];
    const int*   tags   = (const int*)d_in[1];
    const int*   mask   = (const int*)d_in[2];
    const float* trans  = (const float*)d_in[3];
    const float* startt = (const float*)d_in[4];
    const float* endt   = (const float*)d_in[5];

    int B = out_size;                        // 256
    int T = in_sizes[0] / (B * 8);           // 16384, derived from emissions
    int L = (T - 1 + KCH - 1) / KCH;         // steps per chunk (64)

    int sblocks = (B * 32 + 255) / 256;
    crf_score_kernel<<<sblocks, 256>>>(em, tags, mask, trans, startt, endt, B, T);

    int total  = B * KCH;
    int blocks = (total + 127) / 128;
    crf_chunk_kernel<<<blocks, 128>>>(em, mask, trans, B, T, L);

    crf_finalize_kernel<<<B, 32>>>(em, startt, endt, (float*)d_out, B, T);
}

// round 5
// speedup vs baseline: 2.9121x; 2.9121x over previous
#include <cuda_runtime.h>

#define KCH 256      // chunks per batch
#define MAXB 256

__device__ float g_P  [(size_t)MAXB * KCH * 64]; // 8x8 chunk matrices
__device__ float g_cs [MAXB * KCH];              // per-chunk log-scale
__device__ float g_sp [MAXB * KCH];              // per-chunk score partial
__device__ int   g_cnt[MAXB * KCH];              // per-chunk masked count (t>=1)

// ---- packed f32x2 helpers (FFMA2: PTX-only) -------------------------------
__device__ __forceinline__ unsigned long long pk2(float lo, float hi) {
    unsigned long long r;
    asm("mov.b64 %0, {%1, %2};" : "=l"(r) : "f"(lo), "f"(hi));
    return r;
}
__device__ __forceinline__ void upk2(unsigned long long v, float& lo, float& hi) {
    asm("mov.b64 {%0, %1}, %2;" : "=f"(lo), "=f"(hi) : "l"(v));
}
__device__ __forceinline__ unsigned long long mul2(unsigned long long a, unsigned long long b) {
    unsigned long long r;
    asm("mul.rn.f32x2 %0, %1, %2;" : "=l"(r) : "l"(a), "l"(b));
    return r;
}
__device__ __forceinline__ unsigned long long fma2(unsigned long long a, unsigned long long b,
                                                   unsigned long long c) {
    unsigned long long r;
    asm("fma.rn.f32x2 %0, %1, %2, %3;" : "=l"(r) : "l"(a), "l"(b), "l"(c));
    return r;
}

// ---------------------------------------------------------------------------
// Kernel 1: thread = (batch, chunk). 8x8 product of A_t = M * diag(exp(e_t))
// over masked steps (f32x2-packed), fused tag-path score partials.
// ---------------------------------------------------------------------------
__global__ void __launch_bounds__(128) crf_chunk_kernel(
    const float* __restrict__ em,
    const int* __restrict__ tags,
    const int* __restrict__ mask,
    const float* __restrict__ trans,
    int B, int T, int L)
{
    int gid = blockIdx.x * blockDim.x + threadIdx.x;
    if (gid >= B * KCH) return;
    int b = gid >> 8;
    int k = gid & (KCH - 1);

    // M packed by column pairs: M2[i][jj] = { exp(Tr[i][2jj]), exp(Tr[i][2jj+1]) }
    unsigned long long M2[8][4];
#pragma unroll
    for (int i = 0; i < 8; i++)
#pragma unroll
        for (int jj = 0; jj < 4; jj++)
            M2[i][jj] = pk2(__expf(__ldg(&trans[i * 8 + 2 * jj])),
                            __expf(__ldg(&trans[i * 8 + 2 * jj + 1])));

    float P[8][8];
#pragma unroll
    for (int i = 0; i < 8; i++)
#pragma unroll
        for (int j = 0; j < 8; j++)
            P[i][j] = (i == j) ? 1.0f : 0.0f;

    int t0 = 1 + k * L;
    int t1 = t0 + L; if (t1 > T) t1 = T;

    float c = 0.0f, sp = 0.0f;
    int mcnt = 0;
    size_t baseBT = (size_t)b * T;
    int pv = 0;
    if (t0 < T) pv = __ldg(&tags[baseBT + t0 - 1]);

    int cnt = 0;
    for (int t = t0; t < t1; t++) {
        const float4* ep = (const float4*)(em + (baseBT + t) * 8);
        float4 ea = __ldg(ep);
        float4 eb = __ldg(ep + 1);
        float e[8] = {ea.x, ea.y, ea.z, ea.w, eb.x, eb.y, eb.z, eb.w};
        int  tg = __ldg(&tags[baseBT + t]);
        bool mk = (__ldg(&mask[baseBT + t]) != 0);

        if (mk) {
            unsigned long long ev2[4];
#pragma unroll
            for (int jj = 0; jj < 4; jj++)
                ev2[jj] = pk2(__expf(e[2 * jj]), __expf(e[2 * jj + 1]));

#pragma unroll
            for (int i = 0; i < 8; i++) {
                unsigned long long b0 = pk2(P[i][0], P[i][0]);
                unsigned long long a0 = mul2(b0, M2[0][0]);
                unsigned long long a1 = mul2(b0, M2[0][1]);
                unsigned long long a2 = mul2(b0, M2[0][2]);
                unsigned long long a3 = mul2(b0, M2[0][3]);
#pragma unroll
                for (int kk = 1; kk < 8; kk++) {
                    unsigned long long bk = pk2(P[i][kk], P[i][kk]);
                    a0 = fma2(bk, M2[kk][0], a0);
                    a1 = fma2(bk, M2[kk][1], a1);
                    a2 = fma2(bk, M2[kk][2], a2);
                    a3 = fma2(bk, M2[kk][3], a3);
                }
                a0 = mul2(a0, ev2[0]);
                a1 = mul2(a1, ev2[1]);
                a2 = mul2(a2, ev2[2]);
                a3 = mul2(a3, ev2[3]);
                upk2(a0, P[i][0], P[i][1]);
                upk2(a1, P[i][2], P[i][3]);
                upk2(a2, P[i][4], P[i][5]);
                upk2(a3, P[i][6], P[i][7]);
            }
            // fused score: emissions[tag] via select chain + transitions[pv][tg]
            float es = e[0];
#pragma unroll
            for (int j = 1; j < 8; j++) es = (tg == j) ? e[j] : es;
            sp += es + __ldg(&trans[pv * 8 + tg]);
            mcnt++;
        }
        pv = tg;

        if ((++cnt & 3) == 0) {  // rescale every 4 steps
            float s = P[0][0] + P[0][1] + P[0][2] + P[0][3]
                    + P[0][4] + P[0][5] + P[0][6] + P[0][7];
            float r = __fdividef(1.0f, s);
            c += __logf(s);
#pragma unroll
            for (int i = 0; i < 8; i++)
#pragma unroll
                for (int j = 0; j < 8; j++) P[i][j] *= r;
        }
    }
    {
        float s = P[0][0] + P[0][1] + P[0][2] + P[0][3]
                + P[0][4] + P[0][5] + P[0][6] + P[0][7];
        float r = __fdividef(1.0f, s);
        c += __logf(s);
#pragma unroll
        for (int i = 0; i < 8; i++)
#pragma unroll
            for (int j = 0; j < 8; j++) P[i][j] *= r;
    }

    float* dst = &g_P[(size_t)gid * 64];
#pragma unroll
    for (int i = 0; i < 8; i++) {
        ((float4*)dst)[i * 2 + 0] = make_float4(P[i][0], P[i][1], P[i][2], P[i][3]);
        ((float4*)dst)[i * 2 + 1] = make_float4(P[i][4], P[i][5], P[i][6], P[i][7]);
    }
    g_cs [gid] = c;
    g_sp [gid] = sp;
    g_cnt[gid] = mcnt;
}

// ---------------------------------------------------------------------------
// Kernel 2: warp per batch. Lane j (= lane&7; lanes 8..31 replicate) owns
// column j of alpha. Double-buffered fold over 256 chunk matrices, then
// score reduction + NLL.
// ---------------------------------------------------------------------------
__global__ void __launch_bounds__(256) crf_finalize_kernel(
    const float* __restrict__ em,
    const int* __restrict__ tags,
    const int* __restrict__ mask,
    const float* __restrict__ startt,
    const float* __restrict__ endt,
    float* __restrict__ out,
    int B, int T)
{
    int w    = (blockIdx.x * blockDim.x + threadIdx.x) >> 5;
    int lane = threadIdx.x & 31;
    if (w >= B) return;
    const int b = w;
    const int j = lane & 7;
    const unsigned FULL = 0xffffffffu;

    size_t bT = (size_t)b * T;
    float stj = __ldg(&startt[j]);
    float em0 = __ldg(&em[bT * 8 + j]);
    float a   = __expf(stj + em0);
    float c   = 0.0f;

    const float* Pb  = &g_P [(size_t)b * KCH * 64];
    const float* csb = &g_cs[(size_t)b * KCH];

    float mc[8], mn[8];
#pragma unroll
    for (int i = 0; i < 8; i++) mc[i] = __ldg(&Pb[i * 8 + j]);

    for (int k = 0; k < KCH; k++) {
        if (k + 1 < KCH) {
#pragma unroll
            for (int i = 0; i < 8; i++)
                mn[i] = __ldg(&Pb[(size_t)(k + 1) * 64 + i * 8 + j]);
        }
        float r = __shfl_sync(FULL, a, 0) * mc[0];
#pragma unroll
        for (int i = 1; i < 8; i++)
            r = fmaf(__shfl_sync(FULL, a, i), mc[i], r);
        c += __ldg(&csb[k]);

        // rescale every chunk (cheap; keeps fp32 safe)
        float s = r;
        s += __shfl_xor_sync(FULL, s, 1);
        s += __shfl_xor_sync(FULL, s, 2);
        s += __shfl_xor_sync(FULL, s, 4);
        c += __logf(s);
        a = r * __fdividef(1.0f, s);

#pragma unroll
        for (int i = 0; i < 8; i++) mc[i] = mn[i];
    }

    float endj = __ldg(&endt[j]);
    float v = a * __expf(endj);
    v += __shfl_xor_sync(FULL, v, 1);
    v += __shfl_xor_sync(FULL, v, 2);
    v += __shfl_xor_sync(FULL, v, 4);
    float logZ = 0.125f * 0.0f + __logf(v) + c;   // c is lane-uniform

    // ---- score reduction: each lane sums 8 chunks of sp / cnt ----
    const float* spb  = &g_sp [(size_t)b * KCH];
    const int*   cntb = &g_cnt[(size_t)b * KCH];
    float sp = 0.0f;
    int   cnt = 0;
#pragma unroll
    for (int q = 0; q < 8; q++) {
        sp  += __ldg(&spb [lane + 32 * q]);
        cnt += __ldg(&cntb[lane + 32 * q]);
    }
#pragma unroll
    for (int off = 16; off >= 1; off >>= 1) {
        sp  += __shfl_xor_sync(FULL, sp,  off);
        cnt += __shfl_xor_sync(FULL, cnt, off);
    }

    if (lane == 0) {
        cnt += (__ldg(&mask[bT]) != 0) ? 1 : 0;   // include t=0
        int last_valid = cnt - 1;
        int tag0  = __ldg(&tags[bT]);
        int lastt = __ldg(&tags[bT + last_valid]);
        float score = __ldg(&startt[tag0]) + __ldg(&em[bT * 8 + tag0])
                    + sp + __ldg(&endt[lastt]);
        out[b] = logZ - score;
    }
}

// ---------------------------------------------------------------------------
extern "C" void kernel_launch(void* const* d_in, const int* in_sizes, int n_in,
                              void* d_out, int out_size)
{
    const float* em     = (const float*)d_in[0];
    const int*   tags   = (const int*)d_in[1];
    const int*   mask   = (const int*)d_in[2];
    const float* trans  = (const float*)d_in[3];
    const float* startt = (const float*)d_in[4];
    const float* endt   = (const float*)d_in[5];

    int B = out_size;                        // 256
    int T = in_sizes[0] / (B * 8);           // 16384
    int L = (T - 1 + KCH - 1) / KCH;         // 64

    int total  = B * KCH;
    int blocks = (total + 127) / 128;
    crf_chunk_kernel<<<blocks, 128>>>(em, tags, mask, trans, B, T, L);

    int fblocks = (B * 32 + 255) / 256;
    crf_finalize_kernel<<<fblocks, 256>>>(em, tags, mask, startt, endt,
                                          (float*)d_out, B, T);
}

// round 6
// speedup vs baseline: 5.2484x; 1.8023x over previous
#include <cuda_runtime.h>

#define KCH 256      // chunks per batch (must stay 256 for the tree)
#define MAXB 256

__device__ float g_P  [(size_t)MAXB * KCH * 64]; // 8x8 chunk matrices
__device__ float g_cs [MAXB * KCH];              // per-chunk log-scale
__device__ float g_sp [MAXB * KCH];              // per-chunk score partial
__device__ int   g_cnt[MAXB * KCH];              // per-chunk masked count (t>=1)

// ---- packed f32x2 helpers ---------------------------------------------------
__device__ __forceinline__ unsigned long long pk2(float lo, float hi) {
    unsigned long long r;
    asm("mov.b64 %0, {%1, %2};" : "=l"(r) : "f"(lo), "f"(hi));
    return r;
}
__device__ __forceinline__ void upk2(unsigned long long v, float& lo, float& hi) {
    asm("mov.b64 {%0, %1}, %2;" : "=f"(lo), "=f"(hi) : "l"(v));
}
__device__ __forceinline__ unsigned long long mul2(unsigned long long a, unsigned long long b) {
    unsigned long long r;
    asm("mul.rn.f32x2 %0, %1, %2;" : "=l"(r) : "l"(a), "l"(b));
    return r;
}
__device__ __forceinline__ unsigned long long fma2(unsigned long long a, unsigned long long b,
                                                   unsigned long long c) {
    unsigned long long r;
    asm("fma.rn.f32x2 %0, %1, %2, %3;" : "=l"(r) : "l"(a), "l"(b), "l"(c));
    return r;
}

// ---------------------------------------------------------------------------
// one CRF step: P <- P * (M ∘ colscale(exp(e))) if masked; fused score partial
// ---------------------------------------------------------------------------
__device__ __forceinline__ void crf_step(
    float P[8][8], const unsigned long long M2[8][4],
    float4 ea, float4 eb, int tg, int mk,
    const float* __restrict__ trans,
    float& sp, int& mcnt, int& pv)
{
    float e[8] = {ea.x, ea.y, ea.z, ea.w, eb.x, eb.y, eb.z, eb.w};
    if (mk) {
        unsigned long long ev2[4];
#pragma unroll
        for (int jj = 0; jj < 4; jj++)
            ev2[jj] = pk2(__expf(e[2 * jj]), __expf(e[2 * jj + 1]));
#pragma unroll
        for (int i = 0; i < 8; i++) {
            unsigned long long b0 = pk2(P[i][0], P[i][0]);
            unsigned long long a0 = mul2(b0, M2[0][0]);
            unsigned long long a1 = mul2(b0, M2[0][1]);
            unsigned long long a2 = mul2(b0, M2[0][2]);
            unsigned long long a3 = mul2(b0, M2[0][3]);
#pragma unroll
            for (int kk = 1; kk < 8; kk++) {
                unsigned long long bk = pk2(P[i][kk], P[i][kk]);
                a0 = fma2(bk, M2[kk][0], a0);
                a1 = fma2(bk, M2[kk][1], a1);
                a2 = fma2(bk, M2[kk][2], a2);
                a3 = fma2(bk, M2[kk][3], a3);
            }
            a0 = mul2(a0, ev2[0]);
            a1 = mul2(a1, ev2[1]);
            a2 = mul2(a2, ev2[2]);
            a3 = mul2(a3, ev2[3]);
            upk2(a0, P[i][0], P[i][1]);
            upk2(a1, P[i][2], P[i][3]);
            upk2(a2, P[i][4], P[i][5]);
            upk2(a3, P[i][6], P[i][7]);
        }
        float es = e[0];
#pragma unroll
        for (int j = 1; j < 8; j++) es = (tg == j) ? e[j] : es;
        sp += es + __ldg(&trans[pv * 8 + tg]);
        mcnt++;
    }
    pv = tg;
}

__device__ __forceinline__ void rescaleP(float P[8][8], float& c)
{
    float s = P[0][0] + P[0][1] + P[0][2] + P[0][3]
            + P[0][4] + P[0][5] + P[0][6] + P[0][7];
    float r = __fdividef(1.0f, s);
    c += __logf(s);
#pragma unroll
    for (int i = 0; i < 8; i++)
#pragma unroll
        for (int j = 0; j < 8; j++) P[i][j] *= r;
}

// ---------------------------------------------------------------------------
// Kernel 1: thread = (batch, chunk). Groups of 4 steps: int4 tags/mask loads,
// 8 emission float4s issued up front (MLP), rescale per group.
// ---------------------------------------------------------------------------
__global__ void __launch_bounds__(128) crf_chunk_kernel(
    const float* __restrict__ em,
    const int* __restrict__ tags,
    const int* __restrict__ mask,
    const float* __restrict__ trans,
    int B, int T, int L)
{
    int gid = blockIdx.x * blockDim.x + threadIdx.x;
    if (gid >= B * KCH) return;
    int b = gid >> 8;
    int k = gid & (KCH - 1);

    unsigned long long M2[8][4];
#pragma unroll
    for (int i = 0; i < 8; i++)
#pragma unroll
        for (int jj = 0; jj < 4; jj++)
            M2[i][jj] = pk2(__expf(__ldg(&trans[i * 8 + 2 * jj])),
                            __expf(__ldg(&trans[i * 8 + 2 * jj + 1])));

    float P[8][8];
#pragma unroll
    for (int i = 0; i < 8; i++)
#pragma unroll
        for (int j = 0; j < 8; j++)
            P[i][j] = (i == j) ? 1.0f : 0.0f;

    int t0 = 1 + k * L;
    int t1 = t0 + L; if (t1 > T) t1 = T;

    float c = 0.0f, sp = 0.0f;
    int mcnt = 0;
    size_t baseBT = (size_t)b * T;
    int pv = 0;
    if (t0 < T) pv = __ldg(&tags[baseBT + t0 - 1]);

    int t = t0;
    // peel to 4-alignment of t
    while (t < t1 && (t & 3)) {
        const float4* ep = (const float4*)(em + (baseBT + t) * 8);
        float4 ea = __ldg(ep), eb = __ldg(ep + 1);
        int tg = __ldg(&tags[baseBT + t]);
        int mk = __ldg(&mask[baseBT + t]);
        crf_step(P, M2, ea, eb, tg, mk, trans, sp, mcnt, pv);
        t++;
    }
    rescaleP(P, c);

    for (; t + 4 <= t1; t += 4) {
        int4 tg4 = __ldg((const int4*)(tags + baseBT + t));
        int4 mk4 = __ldg((const int4*)(mask + baseBT + t));
        const float4* ep = (const float4*)(em + (baseBT + t) * 8);
        float4 e0a = __ldg(ep + 0), e0b = __ldg(ep + 1);
        float4 e1a = __ldg(ep + 2), e1b = __ldg(ep + 3);
        float4 e2a = __ldg(ep + 4), e2b = __ldg(ep + 5);
        float4 e3a = __ldg(ep + 6), e3b = __ldg(ep + 7);

        crf_step(P, M2, e0a, e0b, tg4.x, mk4.x, trans, sp, mcnt, pv);
        crf_step(P, M2, e1a, e1b, tg4.y, mk4.y, trans, sp, mcnt, pv);
        crf_step(P, M2, e2a, e2b, tg4.z, mk4.z, trans, sp, mcnt, pv);
        crf_step(P, M2, e3a, e3b, tg4.w, mk4.w, trans, sp, mcnt, pv);
        rescaleP(P, c);
    }
    while (t < t1) {
        const float4* ep = (const float4*)(em + (baseBT + t) * 8);
        float4 ea = __ldg(ep), eb = __ldg(ep + 1);
        int tg = __ldg(&tags[baseBT + t]);
        int mk = __ldg(&mask[baseBT + t]);
        crf_step(P, M2, ea, eb, tg, mk, trans, sp, mcnt, pv);
        t++;
    }
    rescaleP(P, c);   // final normalization so stored P is O(1)

    float* dst = &g_P[(size_t)gid * 64];
#pragma unroll
    for (int i = 0; i < 8; i++) {
        ((float4*)dst)[i * 2 + 0] = make_float4(P[i][0], P[i][1], P[i][2], P[i][3]);
        ((float4*)dst)[i * 2 + 1] = make_float4(P[i][4], P[i][5], P[i][6], P[i][7]);
    }
    g_cs [gid] = c;
    g_sp [gid] = sp;
    g_cnt[gid] = mcnt;
}

// ---------------------------------------------------------------------------
// Kernel 2: tree finalize. One block (256 thr) per batch. Level 0 in regs
// (256 gmem matrices -> 128 smem products); 7 in-smem levels; per-node
// rescale; warp 7 reduces sp/cnt concurrently. Thread 0 emits NLL.
// ---------------------------------------------------------------------------
#define MPAD 68   // floats per matrix slot (16B-aligned, de-conflicted)

// C = A(regs rows) * B(packed regs); returns normalized C rows into out smem.
__device__ __forceinline__ void mat_mul_store(
    const float* __restrict__ Arow_src, int a_stride_is_smem, // unused flag style
    const unsigned long long Bp[8][4],
    float* __restrict__ Cdst, float* __restrict__ sc_io, float csum)
{
    // kept for clarity; real work inlined at call sites
}

__global__ void __launch_bounds__(256) crf_tree_finalize(
    const float* __restrict__ em,
    const int* __restrict__ tags,
    const int* __restrict__ mask,
    const float* __restrict__ startt,
    const float* __restrict__ endt,
    float* __restrict__ out,
    int B, int T)
{
    __shared__ float sM[128 * MPAD];
    __shared__ float sC[128];
    __shared__ float s_sp;
    __shared__ int   s_cnt;

    int b   = blockIdx.x;
    int tid = threadIdx.x;
    size_t bK = (size_t)b * KCH;

    // --- concurrent sp/cnt reduction on warp 7 ---
    if (tid >= 224) {
        int l = tid - 224;
        float sp = 0.0f; int cnt = 0;
#pragma unroll
        for (int q = 0; q < 8; q++) {
            sp  += __ldg(&g_sp [bK + l * 8 + q]);
            cnt += __ldg(&g_cnt[bK + l * 8 + q]);
        }
#pragma unroll
        for (int off = 16; off >= 1; off >>= 1) {
            sp  += __shfl_xor_sync(0xffffffffu, sp,  off);
            cnt += __shfl_xor_sync(0xffffffffu, cnt, off);
        }
        if (l == 0) { s_sp = sp; s_cnt = cnt; }
    }

    // --- level 0: gmem pairs -> smem (128 products), in registers ---
    if (tid < 128) {
        const float* Ag = &g_P[(bK + 2 * tid)     * 64];
        const float* Bg = &g_P[(bK + 2 * tid + 1) * 64];

        unsigned long long Bp[8][4];
#pragma unroll
        for (int i = 0; i < 8; i++) {
            float4 lo = __ldg(((const float4*)Bg) + i * 2);
            float4 hi = __ldg(((const float4*)Bg) + i * 2 + 1);
            Bp[i][0] = pk2(lo.x, lo.y); Bp[i][1] = pk2(lo.z, lo.w);
            Bp[i][2] = pk2(hi.x, hi.y); Bp[i][3] = pk2(hi.z, hi.w);
        }
        unsigned long long C[8][4];
#pragma unroll
        for (int i = 0; i < 8; i++) {
            float4 lo = __ldg(((const float4*)Ag) + i * 2);
            float4 hi = __ldg(((const float4*)Ag) + i * 2 + 1);
            float a[8] = {lo.x, lo.y, lo.z, lo.w, hi.x, hi.y, hi.z, hi.w};
            unsigned long long k0 = pk2(a[0], a[0]);
            unsigned long long c0 = mul2(k0, Bp[0][0]);
            unsigned long long c1 = mul2(k0, Bp[0][1]);
            unsigned long long c2 = mul2(k0, Bp[0][2]);
            unsigned long long c3 = mul2(k0, Bp[0][3]);
#pragma unroll
            for (int kk = 1; kk < 8; kk++) {
                unsigned long long kb = pk2(a[kk], a[kk]);
                c0 = fma2(kb, Bp[kk][0], c0);
                c1 = fma2(kb, Bp[kk][1], c1);
                c2 = fma2(kb, Bp[kk][2], c2);
                c3 = fma2(kb, Bp[kk][3], c3);
            }
            C[i][0] = c0; C[i][1] = c1; C[i][2] = c2; C[i][3] = c3;
        }
        // normalize by row-0 sum, write to smem slot tid
        float r0[8];
        upk2(C[0][0], r0[0], r0[1]); upk2(C[0][1], r0[2], r0[3]);
        upk2(C[0][2], r0[4], r0[5]); upk2(C[0][3], r0[6], r0[7]);
        float s = r0[0]+r0[1]+r0[2]+r0[3]+r0[4]+r0[5]+r0[6]+r0[7];
        float r = __fdividef(1.0f, s);
        unsigned long long rr = pk2(r, r);
        float* dst = &sM[tid * MPAD];
#pragma unroll
        for (int i = 0; i < 8; i++) {
            unsigned long long d0 = mul2(C[i][0], rr), d1 = mul2(C[i][1], rr);
            unsigned long long d2 = mul2(C[i][2], rr), d3 = mul2(C[i][3], rr);
            float v0,v1,v2,v3,v4,v5,v6,v7;
            upk2(d0,v0,v1); upk2(d1,v2,v3); upk2(d2,v4,v5); upk2(d3,v6,v7);
            ((float4*)(dst + i * 8))[0] = make_float4(v0,v1,v2,v3);
            ((float4*)(dst + i * 8))[1] = make_float4(v4,v5,v6,v7);
        }
        sC[tid] = __ldg(&g_cs[bK + 2 * tid]) + __ldg(&g_cs[bK + 2 * tid + 1]) + __logf(s);
    }
    __syncthreads();

    // --- levels 1..7 in smem: combine (A=m<<l, B=A+(1<<(l-1))) -> slot A ---
#pragma unroll
    for (int lvl = 1; lvl <= 7; lvl++) {
        int n = 128 >> lvl;
        if (tid < n) {
            int ia = tid << lvl;
            int ib = ia + (1 << (lvl - 1));
            const float* As = &sM[ia * MPAD];
            const float* Bs = &sM[ib * MPAD];

            unsigned long long Bp[8][4];
#pragma unroll
            for (int i = 0; i < 8; i++) {
                float4 lo = ((const float4*)(Bs + i * 8))[0];
                float4 hi = ((const float4*)(Bs + i * 8))[1];
                Bp[i][0] = pk2(lo.x, lo.y); Bp[i][1] = pk2(lo.z, lo.w);
                Bp[i][2] = pk2(hi.x, hi.y); Bp[i][3] = pk2(hi.z, hi.w);
            }
            unsigned long long C[8][4];
#pragma unroll
            for (int i = 0; i < 8; i++) {
                float4 lo = ((const float4*)(As + i * 8))[0];
                float4 hi = ((const float4*)(As + i * 8))[1];
                float a[8] = {lo.x, lo.y, lo.z, lo.w, hi.x, hi.y, hi.z, hi.w};
                unsigned long long k0 = pk2(a[0], a[0]);
                unsigned long long c0 = mul2(k0, Bp[0][0]);
                unsigned long long c1 = mul2(k0, Bp[0][1]);
                unsigned long long c2 = mul2(k0, Bp[0][2]);
                unsigned long long c3 = mul2(k0, Bp[0][3]);
#pragma unroll
                for (int kk = 1; kk < 8; kk++) {
                    unsigned long long kb = pk2(a[kk], a[kk]);
                    c0 = fma2(kb, Bp[kk][0], c0);
                    c1 = fma2(kb, Bp[kk][1], c1);
                    c2 = fma2(kb, Bp[kk][2], c2);
                    c3 = fma2(kb, Bp[kk][3], c3);
                }
                C[i][0] = c0; C[i][1] = c1; C[i][2] = c2; C[i][3] = c3;
            }
            float r0[8];
            upk2(C[0][0], r0[0], r0[1]); upk2(C[0][1], r0[2], r0[3]);
            upk2(C[0][2], r0[4], r0[5]); upk2(C[0][3], r0[6], r0[7]);
            float s = r0[0]+r0[1]+r0[2]+r0[3]+r0[4]+r0[5]+r0[6]+r0[7];
            float r = __fdividef(1.0f, s);
            unsigned long long rr = pk2(r, r);
            float* dst = &sM[ia * MPAD];
#pragma unroll
            for (int i = 0; i < 8; i++) {
                unsigned long long d0 = mul2(C[i][0], rr), d1 = mul2(C[i][1], rr);
                unsigned long long d2 = mul2(C[i][2], rr), d3 = mul2(C[i][3], rr);
                float v0,v1,v2,v3,v4,v5,v6,v7;
                upk2(d0,v0,v1); upk2(d1,v2,v3); upk2(d2,v4,v5); upk2(d3,v6,v7);
                ((float4*)(dst + i * 8))[0] = make_float4(v0,v1,v2,v3);
                ((float4*)(dst + i * 8))[1] = make_float4(v4,v5,v6,v7);
            }
            sC[ia] = sC[ia] + sC[ib] + __logf(s);
        }
        __syncthreads();
    }

    // --- thread 0: alpha0 through root, logZ, score, NLL ---
    if (tid == 0) {
        size_t bT = (size_t)b * T;
        float a[8];
#pragma unroll
        for (int j = 0; j < 8; j++)
            a[j] = __expf(__ldg(&startt[j]) + __ldg(&em[bT * 8 + j]));

        const float* R = &sM[0];
        float v = 0.0f;
#pragma unroll
        for (int j = 0; j < 8; j++) {
            float acc = a[0] * R[0 * 8 + j];
#pragma unroll
            for (int i = 1; i < 8; i++)
                acc = fmaf(a[i], R[i * 8 + j], acc);
            v += acc * __expf(__ldg(&endt[j]));
        }
        float logZ = __logf(v) + sC[0];

        int cnt = s_cnt + ((__ldg(&mask[bT]) != 0) ? 1 : 0);
        int last_valid = cnt - 1;
        int tag0  = __ldg(&tags[bT]);
        int lastt = __ldg(&tags[bT + last_valid]);
        float score = __ldg(&startt[tag0]) + __ldg(&em[bT * 8 + tag0])
                    + s_sp + __ldg(&endt[lastt]);
        out[b] = logZ - score;
    }
}

// ---------------------------------------------------------------------------
extern "C" void kernel_launch(void* const* d_in, const int* in_sizes, int n_in,
                              void* d_out, int out_size)
{
    const float* em     = (const float*)d_in[0];
    const int*   tags   = (const int*)d_in[1];
    const int*   mask   = (const int*)d_in[2];
    const float* trans  = (const float*)d_in[3];
    const float* startt = (const float*)d_in[4];
    const float* endt   = (const float*)d_in[5];

    int B = out_size;                        // 256
    int T = in_sizes[0] / (B * 8);           // 16384
    int L = (T - 1 + KCH - 1) / KCH;         // 64

    int total  = B * KCH;
    int blocks = (total + 127) / 128;
    crf_chunk_kernel<<<blocks, 128>>>(em, tags, mask, trans, B, T, L);

    crf_tree_finalize<<<B, 256>>>(em, tags, mask, startt, endt,
                                  (float*)d_out, B, T);
}

// round 7
// speedup vs baseline: 5.4161x; 1.0319x over previous
#include <cuda_runtime.h>

#define KCH 256      // chunks per batch (tree finalize requires 256)
#define MAXB 256

__device__ float g_P  [(size_t)MAXB * KCH * 64]; // 8x8 chunk matrices
__device__ float g_cs [MAXB * KCH];              // per-chunk log-scale
__device__ float g_sp [MAXB * KCH];              // per-chunk score partial
__device__ int   g_cnt[MAXB * KCH];              // per-chunk masked count (t>=1)

// ---- packed f32x2 helpers ---------------------------------------------------
__device__ __forceinline__ unsigned long long pk2(float lo, float hi) {
    unsigned long long r;
    asm("mov.b64 %0, {%1, %2};" : "=l"(r) : "f"(lo), "f"(hi));
    return r;
}
__device__ __forceinline__ void upk2(unsigned long long v, float& lo, float& hi) {
    asm("mov.b64 {%0, %1}, %2;" : "=f"(lo), "=f"(hi) : "l"(v));
}
__device__ __forceinline__ unsigned long long mul2(unsigned long long a, unsigned long long b) {
    unsigned long long r;
    asm("mul.rn.f32x2 %0, %1, %2;" : "=l"(r) : "l"(a), "l"(b));
    return r;
}
__device__ __forceinline__ unsigned long long fma2(unsigned long long a, unsigned long long b,
                                                   unsigned long long c) {
    unsigned long long r;
    asm("fma.rn.f32x2 %0, %1, %2, %3;" : "=l"(r) : "l"(a), "l"(b), "l"(c));
    return r;
}

// ---------------------------------------------------------------------------
// one CRF step on a 4-row half of P; fused tag-path score (both halves
// compute it; only half 0's copy is stored)
// ---------------------------------------------------------------------------
__device__ __forceinline__ void step4(
    float P[4][8], const unsigned long long M2[8][4],
    float4 ea, float4 eb, int tg, int mk,
    const float* __restrict__ trans,
    float& sp, int& mcnt, int& pv)
{
    float e[8] = {ea.x, ea.y, ea.z, ea.w, eb.x, eb.y, eb.z, eb.w};
    if (mk) {
        unsigned long long ev2[4];
#pragma unroll
        for (int jj = 0; jj < 4; jj++)
            ev2[jj] = pk2(__expf(e[2 * jj]), __expf(e[2 * jj + 1]));
#pragma unroll
        for (int ri = 0; ri < 4; ri++) {
            unsigned long long b0 = pk2(P[ri][0], P[ri][0]);
            unsigned long long a0 = mul2(b0, M2[0][0]);
            unsigned long long a1 = mul2(b0, M2[0][1]);
            unsigned long long a2 = mul2(b0, M2[0][2]);
            unsigned long long a3 = mul2(b0, M2[0][3]);
#pragma unroll
            for (int kk = 1; kk < 8; kk++) {
                unsigned long long bk = pk2(P[ri][kk], P[ri][kk]);
                a0 = fma2(bk, M2[kk][0], a0);
                a1 = fma2(bk, M2[kk][1], a1);
                a2 = fma2(bk, M2[kk][2], a2);
                a3 = fma2(bk, M2[kk][3], a3);
            }
            a0 = mul2(a0, ev2[0]);
            a1 = mul2(a1, ev2[1]);
            a2 = mul2(a2, ev2[2]);
            a3 = mul2(a3, ev2[3]);
            upk2(a0, P[ri][0], P[ri][1]);
            upk2(a1, P[ri][2], P[ri][3]);
            upk2(a2, P[ri][4], P[ri][5]);
            upk2(a3, P[ri][6], P[ri][7]);
        }
        float es = e[0];
#pragma unroll
        for (int j = 1; j < 8; j++) es = (tg == j) ? e[j] : es;
        sp += es + __ldg(&trans[pv * 8 + tg]);
        mcnt++;
    }
    pv = tg;
}

// rescale using the full-matrix row-0 sum (lives in half 0; broadcast to pair)
__device__ __forceinline__ void rescale4(float P[4][8], float& c, int half)
{
    const unsigned FULL = 0xffffffffu;
    float s = P[0][0] + P[0][1] + P[0][2] + P[0][3]
            + P[0][4] + P[0][5] + P[0][6] + P[0][7];
    float sx = __shfl_xor_sync(FULL, s, 1);
    s = half ? sx : s;
    float r = __fdividef(1.0f, s);
    c += __logf(s);
#pragma unroll
    for (int ri = 0; ri < 4; ri++)
#pragma unroll
        for (int j = 0; j < 8; j++) P[ri][j] *= r;
}

// ---------------------------------------------------------------------------
// Kernel 1: lane pair = (batch, chunk); each lane carries 4 rows of P.
// Pair shares emission/tag/mask loads via shfl_xor(1).
// ---------------------------------------------------------------------------
__global__ void __launch_bounds__(128) crf_chunk_kernel(
    const float* __restrict__ em,
    const int* __restrict__ tags,
    const int* __restrict__ mask,
    const float* __restrict__ trans,
    int B, int T, int L)
{
    int gid = blockIdx.x * blockDim.x + threadIdx.x;
    if (gid >= B * KCH * 2) return;
    int chunkid = gid >> 1;
    int half    = gid & 1;
    int b = chunkid >> 8;
    int k = chunkid & (KCH - 1);
    const unsigned FULL = 0xffffffffu;

    unsigned long long M2[8][4];
#pragma unroll
    for (int i = 0; i < 8; i++)
#pragma unroll
        for (int jj = 0; jj < 4; jj++)
            M2[i][jj] = pk2(__expf(__ldg(&trans[i * 8 + 2 * jj])),
                            __expf(__ldg(&trans[i * 8 + 2 * jj + 1])));

    float P[4][8];
#pragma unroll
    for (int ri = 0; ri < 4; ri++)
#pragma unroll
        for (int j = 0; j < 8; j++)
            P[ri][j] = ((ri + 4 * half) == j) ? 1.0f : 0.0f;

    int t0 = 1 + k * L;
    int t1 = t0 + L; if (t1 > T) t1 = T;

    float c = 0.0f, sp = 0.0f;
    int mcnt = 0;
    size_t baseBT = (size_t)b * T;
    int pv = 0;
    if (t0 < T) pv = __ldg(&tags[baseBT + t0 - 1]);

    int t = t0;
    // peel to 4-alignment (both lanes load the step directly)
    while (t < t1 && (t & 3)) {
        const float4* ep = (const float4*)(em + (baseBT + t) * 8);
        float4 ea = __ldg(ep), eb = __ldg(ep + 1);
        int tg = __ldg(&tags[baseBT + t]);
        int mk = __ldg(&mask[baseBT + t]);
        step4(P, M2, ea, eb, tg, mk, trans, sp, mcnt, pv);
        t++;
    }
    rescale4(P, c, half);

    for (; t + 4 <= t1; t += 4) {
        // pair-cooperative emission load: half0 -> steps t,t+1; half1 -> t+2,t+3
        const float4* ep = (const float4*)(em + (baseBT + t) * 8);
        float4 mine[4], oth[4];
#pragma unroll
        for (int q = 0; q < 4; q++) mine[q] = __ldg(ep + half * 4 + q);
#pragma unroll
        for (int q = 0; q < 4; q++) {
            oth[q].x = __shfl_xor_sync(FULL, mine[q].x, 1);
            oth[q].y = __shfl_xor_sync(FULL, mine[q].y, 1);
            oth[q].z = __shfl_xor_sync(FULL, mine[q].z, 1);
            oth[q].w = __shfl_xor_sync(FULL, mine[q].w, 1);
        }
        float4 F[8];
#pragma unroll
        for (int q = 0; q < 4; q++) {
            F[q]     = half ? oth[q]  : mine[q];
            F[4 + q] = half ? mine[q] : oth[q];
        }

        // pair-cooperative tags/mask: half0 loads tags, half1 loads mask
        int4 myi = half ? __ldg((const int4*)(mask + baseBT + t))
                        : __ldg((const int4*)(tags + baseBT + t));
        int4 oti;
        oti.x = __shfl_xor_sync(FULL, myi.x, 1);
        oti.y = __shfl_xor_sync(FULL, myi.y, 1);
        oti.z = __shfl_xor_sync(FULL, myi.z, 1);
        oti.w = __shfl_xor_sync(FULL, myi.w, 1);
        int4 tg4 = half ? oti : myi;
        int4 mk4 = half ? myi : oti;

        step4(P, M2, F[0], F[1], tg4.x, mk4.x, trans, sp, mcnt, pv);
        step4(P, M2, F[2], F[3], tg4.y, mk4.y, trans, sp, mcnt, pv);
        step4(P, M2, F[4], F[5], tg4.z, mk4.z, trans, sp, mcnt, pv);
        step4(P, M2, F[6], F[7], tg4.w, mk4.w, trans, sp, mcnt, pv);
        rescale4(P, c, half);
    }
    while (t < t1) {
        const float4* ep = (const float4*)(em + (baseBT + t) * 8);
        float4 ea = __ldg(ep), eb = __ldg(ep + 1);
        int tg = __ldg(&tags[baseBT + t]);
        int mk = __ldg(&mask[baseBT + t]);
        step4(P, M2, ea, eb, tg, mk, trans, sp, mcnt, pv);
        t++;
    }
    rescale4(P, c, half);   // final normalization so stored P is O(1)

    float* dst = &g_P[(size_t)chunkid * 64 + half * 32];
#pragma unroll
    for (int ri = 0; ri < 4; ri++) {
        ((float4*)dst)[ri * 2 + 0] = make_float4(P[ri][0], P[ri][1], P[ri][2], P[ri][3]);
        ((float4*)dst)[ri * 2 + 1] = make_float4(P[ri][4], P[ri][5], P[ri][6], P[ri][7]);
    }
    if (!half) {
        g_cs [chunkid] = c;
        g_sp [chunkid] = sp;
        g_cnt[chunkid] = mcnt;
    }
}

// ---------------------------------------------------------------------------
// Kernel 2: tree finalize (unchanged from R6). One block per batch.
// ---------------------------------------------------------------------------
#define MPAD 68

__global__ void __launch_bounds__(256) crf_tree_finalize(
    const float* __restrict__ em,
    const int* __restrict__ tags,
    const int* __restrict__ mask,
    const float* __restrict__ startt,
    const float* __restrict__ endt,
    float* __restrict__ out,
    int B, int T)
{
    __shared__ float sM[128 * MPAD];
    __shared__ float sC[128];
    __shared__ float s_sp;
    __shared__ int   s_cnt;

    int b   = blockIdx.x;
    int tid = threadIdx.x;
    size_t bK = (size_t)b * KCH;

    if (tid >= 224) {
        int l = tid - 224;
        float sp = 0.0f; int cnt = 0;
#pragma unroll
        for (int q = 0; q < 8; q++) {
            sp  += __ldg(&g_sp [bK + l * 8 + q]);
            cnt += __ldg(&g_cnt[bK + l * 8 + q]);
        }
#pragma unroll
        for (int off = 16; off >= 1; off >>= 1) {
            sp  += __shfl_xor_sync(0xffffffffu, sp,  off);
            cnt += __shfl_xor_sync(0xffffffffu, cnt, off);
        }
        if (l == 0) { s_sp = sp; s_cnt = cnt; }
    }

    if (tid < 128) {
        const float* Ag = &g_P[(bK + 2 * tid)     * 64];
        const float* Bg = &g_P[(bK + 2 * tid + 1) * 64];

        unsigned long long Bp[8][4];
#pragma unroll
        for (int i = 0; i < 8; i++) {
            float4 lo = __ldg(((const float4*)Bg) + i * 2);
            float4 hi = __ldg(((const float4*)Bg) + i * 2 + 1);
            Bp[i][0] = pk2(lo.x, lo.y); Bp[i][1] = pk2(lo.z, lo.w);
            Bp[i][2] = pk2(hi.x, hi.y); Bp[i][3] = pk2(hi.z, hi.w);
        }
        unsigned long long C[8][4];
#pragma unroll
        for (int i = 0; i < 8; i++) {
            float4 lo = __ldg(((const float4*)Ag) + i * 2);
            float4 hi = __ldg(((const float4*)Ag) + i * 2 + 1);
            float a[8] = {lo.x, lo.y, lo.z, lo.w, hi.x, hi.y, hi.z, hi.w};
            unsigned long long k0 = pk2(a[0], a[0]);
            unsigned long long c0 = mul2(k0, Bp[0][0]);
            unsigned long long c1 = mul2(k0, Bp[0][1]);
            unsigned long long c2 = mul2(k0, Bp[0][2]);
            unsigned long long c3 = mul2(k0, Bp[0][3]);
#pragma unroll
            for (int kk = 1; kk < 8; kk++) {
                unsigned long long kb = pk2(a[kk], a[kk]);
                c0 = fma2(kb, Bp[kk][0], c0);
                c1 = fma2(kb, Bp[kk][1], c1);
                c2 = fma2(kb, Bp[kk][2], c2);
                c3 = fma2(kb, Bp[kk][3], c3);
            }
            C[i][0] = c0; C[i][1] = c1; C[i][2] = c2; C[i][3] = c3;
        }
        float r0[8];
        upk2(C[0][0], r0[0], r0[1]); upk2(C[0][1], r0[2], r0[3]);
        upk2(C[0][2], r0[4], r0[5]); upk2(C[0][3], r0[6], r0[7]);
        float s = r0[0]+r0[1]+r0[2]+r0[3]+r0[4]+r0[5]+r0[6]+r0[7];
        float r = __fdividef(1.0f, s);
        unsigned long long rr = pk2(r, r);
        float* dst = &sM[tid * MPAD];
#pragma unroll
        for (int i = 0; i < 8; i++) {
            unsigned long long d0 = mul2(C[i][0], rr), d1 = mul2(C[i][1], rr);
            unsigned long long d2 = mul2(C[i][2], rr), d3 = mul2(C[i][3], rr);
            float v0,v1,v2,v3,v4,v5,v6,v7;
            upk2(d0,v0,v1); upk2(d1,v2,v3); upk2(d2,v4,v5); upk2(d3,v6,v7);
            ((float4*)(dst + i * 8))[0] = make_float4(v0,v1,v2,v3);
            ((float4*)(dst + i * 8))[1] = make_float4(v4,v5,v6,v7);
        }
        sC[tid] = __ldg(&g_cs[bK + 2 * tid]) + __ldg(&g_cs[bK + 2 * tid + 1]) + __logf(s);
    }
    __syncthreads();

#pragma unroll
    for (int lvl = 1; lvl <= 7; lvl++) {
        int n = 128 >> lvl;
        if (tid < n) {
            int ia = tid << lvl;
            int ib = ia + (1 << (lvl - 1));
            const float* As = &sM[ia * MPAD];
            const float* Bs = &sM[ib * MPAD];

            unsigned long long Bp[8][4];
#pragma unroll
            for (int i = 0; i < 8; i++) {
                float4 lo = ((const float4*)(Bs + i * 8))[0];
                float4 hi = ((const float4*)(Bs + i * 8))[1];
                Bp[i][0] = pk2(lo.x, lo.y); Bp[i][1] = pk2(lo.z, lo.w);
                Bp[i][2] = pk2(hi.x, hi.y); Bp[i][3] = pk2(hi.z, hi.w);
            }
            unsigned long long C[8][4];
#pragma unroll
            for (int i = 0; i < 8; i++) {
                float4 lo = ((const float4*)(As + i * 8))[0];
                float4 hi = ((const float4*)(As + i * 8))[1];
                float a[8] = {lo.x, lo.y, lo.z, lo.w, hi.x, hi.y, hi.z, hi.w};
                unsigned long long k0 = pk2(a[0], a[0]);
                unsigned long long c0 = mul2(k0, Bp[0][0]);
                unsigned long long c1 = mul2(k0, Bp[0][1]);
                unsigned long long c2 = mul2(k0, Bp[0][2]);
                unsigned long long c3 = mul2(k0, Bp[0][3]);
#pragma unroll
                for (int kk = 1; kk < 8; kk++) {
                    unsigned long long kb = pk2(a[kk], a[kk]);
                    c0 = fma2(kb, Bp[kk][0], c0);
                    c1 = fma2(kb, Bp[kk][1], c1);
                    c2 = fma2(kb, Bp[kk][2], c2);
                    c3 = fma2(kb, Bp[kk][3], c3);
                }
                C[i][0] = c0; C[i][1] = c1; C[i][2] = c2; C[i][3] = c3;
            }
            float r0[8];
            upk2(C[0][0], r0[0], r0[1]); upk2(C[0][1], r0[2], r0[3]);
            upk2(C[0][2], r0[4], r0[5]); upk2(C[0][3], r0[6], r0[7]);
            float s = r0[0]+r0[1]+r0[2]+r0[3]+r0[4]+r0[5]+r0[6]+r0[7];
            float r = __fdividef(1.0f, s);
            unsigned long long rr = pk2(r, r);
            float* dst = &sM[ia * MPAD];
#pragma unroll
            for (int i = 0; i < 8; i++) {
                unsigned long long d0 = mul2(C[i][0], rr), d1 = mul2(C[i][1], rr);
                unsigned long long d2 = mul2(C[i][2], rr), d3 = mul2(C[i][3], rr);
                float v0,v1,v2,v3,v4,v5,v6,v7;
                upk2(d0,v0,v1); upk2(d1,v2,v3); upk2(d2,v4,v5); upk2(d3,v6,v7);
                ((float4*)(dst + i * 8))[0] = make_float4(v0,v1,v2,v3);
                ((float4*)(dst + i * 8))[1] = make_float4(v4,v5,v6,v7);
            }
            sC[ia] = sC[ia] + sC[ib] + __logf(s);
        }
        __syncthreads();
    }

    if (tid == 0) {
        size_t bT = (size_t)b * T;
        float a[8];
#pragma unroll
        for (int j = 0; j < 8; j++)
            a[j] = __expf(__ldg(&startt[j]) + __ldg(&em[bT * 8 + j]));

        const float* R = &sM[0];
        float v = 0.0f;
#pragma unroll
        for (int j = 0; j < 8; j++) {
            float acc = a[0] * R[0 * 8 + j];
#pragma unroll
            for (int i = 1; i < 8; i++)
                acc = fmaf(a[i], R[i * 8 + j], acc);
            v += acc * __expf(__ldg(&endt[j]));
        }
        float logZ = __logf(v) + sC[0];

        int cnt = s_cnt + ((__ldg(&mask[bT]) != 0) ? 1 : 0);
        int last_valid = cnt - 1;
        int tag0  = __ldg(&tags[bT]);
        int lastt = __ldg(&tags[bT + last_valid]);
        float score = __ldg(&startt[tag0]) + __ldg(&em[bT * 8 + tag0])
                    + s_sp + __ldg(&endt[lastt]);
        out[b] = logZ - score;
    }
}

// ---------------------------------------------------------------------------
extern "C" void kernel_launch(void* const* d_in, const int* in_sizes, int n_in,
                              void* d_out, int out_size)
{
    const float* em     = (const float*)d_in[0];
    const int*   tags   = (const int*)d_in[1];
    const int*   mask   = (const int*)d_in[2];
    const float* trans  = (const float*)d_in[3];
    const float* startt = (const float*)d_in[4];
    const float* endt   = (const float*)d_in[5];

    int B = out_size;                        // 256
    int T = in_sizes[0] / (B * 8);           // 16384
    int L = (T - 1 + KCH - 1) / KCH;         // 64

    int total  = B * KCH * 2;                // lane pairs
    int blocks = (total + 127) / 128;
    crf_chunk_kernel<<<blocks, 128>>>(em, tags, mask, trans, B, T, L);

    crf_tree_finalize<<<B, 256>>>(em, tags, mask, startt, endt,
                                  (float*)d_out, B, T);
}

// round 8
// speedup vs baseline: 10.5794x; 1.9533x over previous
#include <cuda_runtime.h>

#define L    64      // steps per chunk
#define KCH  256     // chunks per batch (T / L)
#define MAXB 256
#define OVLG 4       // overlap groups (16 warm-up steps)
#define CPB  128     // chunks (threads) per block
#define RS   36      // smem row stride in floats (32 data + 4 pad)

__device__ float g_c  [MAXB * KCH];   // per-chunk log-growth (k=0 includes log S0)
__device__ float g_sp [MAXB * KCH];   // per-chunk score partial
__device__ int   g_cnt[MAXB * KCH];   // per-chunk masked count (t>=1)
__device__ float g_nf [MAXB * 8];     // normalized final alpha direction

// ---- packed f32x2 helpers ---------------------------------------------------
__device__ __forceinline__ unsigned long long pk2(float lo, float hi) {
    unsigned long long r;
    asm("mov.b64 %0, {%1, %2};" : "=l"(r) : "f"(lo), "f"(hi));
    return r;
}
__device__ __forceinline__ void upk2(unsigned long long v, float& lo, float& hi) {
    asm("mov.b64 {%0, %1}, %2;" : "=f"(lo), "=f"(hi) : "l"(v));
}
__device__ __forceinline__ unsigned long long mul2(unsigned long long a, unsigned long long b) {
    unsigned long long r;
    asm("mul.rn.f32x2 %0, %1, %2;" : "=l"(r) : "l"(a), "l"(b));
    return r;
}
__device__ __forceinline__ unsigned long long fma2(unsigned long long a, unsigned long long b,
                                                   unsigned long long c) {
    unsigned long long r;
    asm("fma.rn.f32x2 %0, %1, %2, %3;" : "=l"(r) : "l"(a), "l"(b), "l"(c));
    return r;
}

// v <- (v^T M) ∘ exp(e)   (8-vector step, packed column pairs)
__device__ __forceinline__ void vstep(float v[8], const unsigned long long M2[8][4],
                                      const float e[8])
{
    unsigned long long ev0 = pk2(__expf(e[0]), __expf(e[1]));
    unsigned long long ev1 = pk2(__expf(e[2]), __expf(e[3]));
    unsigned long long ev2 = pk2(__expf(e[4]), __expf(e[5]));
    unsigned long long ev3 = pk2(__expf(e[6]), __expf(e[7]));

    unsigned long long vb = pk2(v[0], v[0]);
    unsigned long long a0 = mul2(vb, M2[0][0]);
    unsigned long long a1 = mul2(vb, M2[0][1]);
    unsigned long long a2 = mul2(vb, M2[0][2]);
    unsigned long long a3 = mul2(vb, M2[0][3]);
#pragma unroll
    for (int i = 1; i < 8; i++) {
        vb = pk2(v[i], v[i]);
        a0 = fma2(vb, M2[i][0], a0);
        a1 = fma2(vb, M2[i][1], a1);
        a2 = fma2(vb, M2[i][2], a2);
        a3 = fma2(vb, M2[i][3], a3);
    }
    a0 = mul2(a0, ev0);
    a1 = mul2(a1, ev1);
    a2 = mul2(a2, ev2);
    a3 = mul2(a3, ev3);
    upk2(a0, v[0], v[1]);
    upk2(a1, v[2], v[3]);
    upk2(a2, v[4], v[5]);
    upk2(a3, v[6], v[7]);
}

// ---------------------------------------------------------------------------
// Kernel 1: thread = chunk. Vector recurrence with 16-step overlap warm-up.
// Emissions staged via smem tiles (coalesced). Fused tag-path score.
// ---------------------------------------------------------------------------
__global__ void __launch_bounds__(CPB) crf_chunk_vec(
    const float* __restrict__ em,
    const int* __restrict__ tags,
    const int* __restrict__ mask,
    const float* __restrict__ trans,
    const float* __restrict__ startt,
    int B, int T)
{
    __shared__ float sE[CPB * RS];

    int tid = threadIdx.x;
    int b   = blockIdx.x >> 1;
    int k0  = (blockIdx.x & 1) * CPB;
    int k   = k0 + tid;
    size_t bT = (size_t)b * T;
    const float* emB = em + bT * 8;

    unsigned long long M2[8][4];
#pragma unroll
    for (int i = 0; i < 8; i++)
#pragma unroll
        for (int jj = 0; jj < 4; jj++)
            M2[i][jj] = pk2(__expf(__ldg(&trans[i * 8 + 2 * jj])),
                            __expf(__ldg(&trans[i * 8 + 2 * jj + 1])));

    float v[8];
#pragma unroll
    for (int j = 0; j < 8; j++) v[j] = 0.125f;   // arbitrary positive start (k>0)

    float c = 0.0f, sp = 0.0f;
    int mcnt = 0;
    int pv = __ldg(&tags[bT + (k > 0 ? k * L - 1 : 0)]);

    for (int g = -OVLG; g < L / 4; g++) {
        __syncthreads();   // previous tile fully consumed
        // --- cooperative stage: 128 rows x (4 steps x 8 floats) ---
#pragma unroll
        for (int m = 0; m < 8; m++) {
            int idx = m * CPB + tid;
            int r  = idx >> 3;
            int qq = idx & 7;
            int tr = (k0 + r) * L + 4 * g;
            if (tr < 0) tr = 0;
            float4 val = __ldg((const float4*)(emB + (size_t)tr * 8) + qq);
            *((float4*)(sE + r * RS) + qq) = val;
        }
        __syncthreads();

        int tb = k * L + 4 * g;
        const float* erow = sE + tid * RS;

        if (g == 0) {
            if (k == 0) {
                // exact alpha0 = exp(start + em[0]) (row t=0 is in this tile)
                float e0[8];
                *(float4*)(e0)     = *((const float4*)erow);
                *(float4*)(e0 + 4) = *((const float4*)erow + 1);
                float s = 0.0f;
#pragma unroll
                for (int j = 0; j < 8; j++) {
                    v[j] = __expf(__ldg(&startt[j]) + e0[j]);
                    s += v[j];
                }
                c = __logf(s);
                float r = __fdividef(1.0f, s);
#pragma unroll
                for (int j = 0; j < 8; j++) v[j] *= r;
            } else {
                // chunk boundary: normalize, reset growth accumulator
                float s = v[0]+v[1]+v[2]+v[3]+v[4]+v[5]+v[6]+v[7];
                float r = __fdividef(1.0f, s);
                c = 0.0f;
#pragma unroll
                for (int j = 0; j < 8; j++) v[j] *= r;
            }
        }

        if (g >= 0) {
            int4 tg4 = __ldg((const int4*)(tags + bT + tb));
            int4 mk4 = __ldg((const int4*)(mask + bT + tb));
            int tgA[4] = {tg4.x, tg4.y, tg4.z, tg4.w};
            int mkA[4] = {mk4.x, mk4.y, mk4.z, mk4.w};
#pragma unroll
            for (int q = 0; q < 4; q++) {
                float e[8];
                *(float4*)(e)     = *((const float4*)erow + 2 * q);
                *(float4*)(e + 4) = *((const float4*)erow + 2 * q + 1);
                int tg = tgA[q];
                if (mkA[q] && (tb + q >= 1)) {
                    vstep(v, M2, e);
                    float es = e[0];
#pragma unroll
                    for (int j = 1; j < 8; j++) es = (tg == j) ? e[j] : es;
                    sp += es + __ldg(&trans[pv * 8 + tg]);
                    mcnt++;
                }
                pv = tg;
            }
        } else if (tb >= 0) {   // overlap warm-up (k>0 only)
            int4 mk4 = __ldg((const int4*)(mask + bT + tb));
            int mkA[4] = {mk4.x, mk4.y, mk4.z, mk4.w};
#pragma unroll
            for (int q = 0; q < 4; q++) {
                float e[8];
                *(float4*)(e)     = *((const float4*)erow + 2 * q);
                *(float4*)(e + 4) = *((const float4*)erow + 2 * q + 1);
                if (mkA[q]) vstep(v, M2, e);
            }
        }

        // group-end rescale (growth accumulates; overlap pollution is reset at g==0)
        {
            float s = v[0]+v[1]+v[2]+v[3]+v[4]+v[5]+v[6]+v[7];
            float r = __fdividef(1.0f, s);
            c += __logf(s);
#pragma unroll
            for (int j = 0; j < 8; j++) v[j] *= r;
        }
    }

    size_t gidx = (size_t)b * KCH + k;
    g_c  [gidx] = c;
    g_sp [gidx] = sp;
    g_cnt[gidx] = mcnt;
    if (k == KCH - 1) {
#pragma unroll
        for (int j = 0; j < 8; j++) g_nf[b * 8 + j] = v[j];
    }
}

// ---------------------------------------------------------------------------
// Kernel 2: trivial finalize. Block per batch: reduce 256 (c, sp, cnt),
// add end term, emit NLL.
// ---------------------------------------------------------------------------
__global__ void __launch_bounds__(256) crf_final(
    const float* __restrict__ em,
    const int* __restrict__ tags,
    const int* __restrict__ mask,
    const float* __restrict__ startt,
    const float* __restrict__ endt,
    float* __restrict__ out,
    int B, int T)
{
    __shared__ float sC[256];
    __shared__ float sS[256];
    __shared__ int   sN[256];

    int b   = blockIdx.x;
    int tid = threadIdx.x;
    size_t bK = (size_t)b * KCH;

    sC[tid] = __ldg(&g_c  [bK + tid]);
    sS[tid] = __ldg(&g_sp [bK + tid]);
    sN[tid] = __ldg(&g_cnt[bK + tid]);
    __syncthreads();

#pragma unroll
    for (int s = 128; s > 0; s >>= 1) {
        if (tid < s) {
            sC[tid] += sC[tid + s];
            sS[tid] += sS[tid + s];
            sN[tid] += sN[tid + s];
        }
        __syncthreads();
    }

    if (tid == 0) {
        size_t bT = (size_t)b * T;
        float vsum = 0.0f;
#pragma unroll
        for (int j = 0; j < 8; j++)
            vsum += g_nf[b * 8 + j] * __expf(__ldg(&endt[j]));
        float logZ = sC[0] + __logf(vsum);

        int cnt = sN[0] + ((__ldg(&mask[bT]) != 0) ? 1 : 0);
        int last_valid = cnt - 1;
        int tag0  = __ldg(&tags[bT]);
        int lastt = __ldg(&tags[bT + last_valid]);
        float score = __ldg(&startt[tag0]) + __ldg(&em[bT * 8 + tag0])
                    + sS[0] + __ldg(&endt[lastt]);
        out[b] = logZ - score;
    }
}

// ---------------------------------------------------------------------------
extern "C" void kernel_launch(void* const* d_in, const int* in_sizes, int n_in,
                              void* d_out, int out_size)
{
    const float* em     = (const float*)d_in[0];
    const int*   tags   = (const int*)d_in[1];
    const int*   mask   = (const int*)d_in[2];
    const float* trans  = (const float*)d_in[3];
    const float* startt = (const float*)d_in[4];
    const float* endt   = (const float*)d_in[5];

    int B = out_size;                 // 256
    int T = in_sizes[0] / (B * 8);    // 16384 (= KCH * L)

    int nblocks = B * (KCH / CPB);    // 512
    crf_chunk_vec<<<nblocks, CPB>>>(em, tags, mask, trans, startt, B, T);

    crf_final<<<B, 256>>>(em, tags, mask, startt, endt, (float*)d_out, B, T);
}

// round 9
// speedup vs baseline: 11.7092x; 1.1068x over previous
#include <cuda_runtime.h>

#define L    64      // steps per chunk
#define KCH  256     // chunks per batch (T / L)
#define MAXB 256
#define OVLG 2       // overlap groups (8 warm-up steps)
#define CPB  128     // chunks (threads) per block
#define RS   36      // smem row stride in floats (32 data + 4 pad)

__device__ float g_c  [MAXB * KCH];   // per-chunk log-growth
__device__ float g_sp [MAXB * KCH];   // per-chunk score partial
__device__ int   g_cnt[MAXB * KCH];   // per-chunk masked count (t>=1)
__device__ float g_nf [MAXB * 8];     // normalized final alpha direction

// ---- packed f32x2 helpers ---------------------------------------------------
__device__ __forceinline__ unsigned long long pk2(float lo, float hi) {
    unsigned long long r;
    asm("mov.b64 %0, {%1, %2};" : "=l"(r) : "f"(lo), "f"(hi));
    return r;
}
__device__ __forceinline__ void upk2(unsigned long long v, float& lo, float& hi) {
    asm("mov.b64 {%0, %1}, %2;" : "=f"(lo), "=f"(hi) : "l"(v));
}
__device__ __forceinline__ unsigned long long mul2(unsigned long long a, unsigned long long b) {
    unsigned long long r;
    asm("mul.rn.f32x2 %0, %1, %2;" : "=l"(r) : "l"(a), "l"(b));
    return r;
}
__device__ __forceinline__ unsigned long long fma2(unsigned long long a, unsigned long long b,
                                                   unsigned long long c) {
    unsigned long long r;
    asm("fma.rn.f32x2 %0, %1, %2, %3;" : "=l"(r) : "l"(a), "l"(b), "l"(c));
    return r;
}

// v <- (v^T M) ∘ exp(e)
__device__ __forceinline__ void vstep(float v[8], const unsigned long long M2[8][4],
                                      const float e[8])
{
    unsigned long long ev0 = pk2(__expf(e[0]), __expf(e[1]));
    unsigned long long ev1 = pk2(__expf(e[2]), __expf(e[3]));
    unsigned long long ev2 = pk2(__expf(e[4]), __expf(e[5]));
    unsigned long long ev3 = pk2(__expf(e[6]), __expf(e[7]));

    unsigned long long vb = pk2(v[0], v[0]);
    unsigned long long a0 = mul2(vb, M2[0][0]);
    unsigned long long a1 = mul2(vb, M2[0][1]);
    unsigned long long a2 = mul2(vb, M2[0][2]);
    unsigned long long a3 = mul2(vb, M2[0][3]);
#pragma unroll
    for (int i = 1; i < 8; i++) {
        vb = pk2(v[i], v[i]);
        a0 = fma2(vb, M2[i][0], a0);
        a1 = fma2(vb, M2[i][1], a1);
        a2 = fma2(vb, M2[i][2], a2);
        a3 = fma2(vb, M2[i][3], a3);
    }
    a0 = mul2(a0, ev0);
    a1 = mul2(a1, ev1);
    a2 = mul2(a2, ev2);
    a3 = mul2(a3, ev3);
    upk2(a0, v[0], v[1]);
    upk2(a1, v[2], v[3]);
    upk2(a2, v[4], v[5]);
    upk2(a3, v[6], v[7]);
}

// ---------------------------------------------------------------------------
// Kernel 1: thread = chunk. Vector recurrence with 8-step overlap warm-up.
// Double-buffered smem staging: issue next tile's LDGs, compute current,
// store to alternate buffer, one syncthreads per group.
// ---------------------------------------------------------------------------
__global__ void __launch_bounds__(CPB) crf_chunk_vec(
    const float* __restrict__ em,
    const int* __restrict__ tags,
    const int* __restrict__ mask,
    const float* __restrict__ trans,
    const float* __restrict__ startt,
    int B, int T)
{
    __shared__ float sE[2][CPB * RS];

    int tid = threadIdx.x;
    int b   = blockIdx.x >> 1;
    int k0  = (blockIdx.x & 1) * CPB;
    int k   = k0 + tid;
    size_t bT = (size_t)b * T;
    const float* emB = em + bT * 8;

    // staging geometry for this thread (fixed across groups)
    const int sr  = ((0 * CPB + tid) >> 3);          // unused placeholder
    (void)sr;

    unsigned long long M2[8][4];
#pragma unroll
    for (int i = 0; i < 8; i++)
#pragma unroll
        for (int jj = 0; jj < 4; jj++)
            M2[i][jj] = pk2(__expf(__ldg(&trans[i * 8 + 2 * jj])),
                            __expf(__ldg(&trans[i * 8 + 2 * jj + 1])));

    float v[8];
#pragma unroll
    for (int j = 0; j < 8; j++) v[j] = 0.125f;

    float c = 0.0f, sp = 0.0f;
    int mcnt = 0;
    int pv = __ldg(&tags[bT + (k > 0 ? k * L - 1 : 0)]);

    float4 stg[8];
    // preload first tile (g = -OVLG)
#pragma unroll
    for (int m = 0; m < 8; m++) {
        int idx = m * CPB + tid;
        int r   = idx >> 3;
        int qq  = idx & 7;
        int tr  = (k0 + r) * L + 4 * (-OVLG);
        if (tr < 0) tr = 0;
        stg[m] = __ldg((const float4*)(emB + (size_t)tr * 8) + qq);
    }
#pragma unroll
    for (int m = 0; m < 8; m++) {
        int idx = m * CPB + tid;
        *((float4*)(sE[0] + (idx >> 3) * RS) + (idx & 7)) = stg[m];
    }
    __syncthreads();

    for (int g = -OVLG; g < L / 4; g++) {
        int cur = (g + OVLG) & 1;

        // issue next tile's LDGs before compute (latency hidden under compute)
        bool more = (g + 1 < L / 4);
        if (more) {
#pragma unroll
            for (int m = 0; m < 8; m++) {
                int idx = m * CPB + tid;
                int r   = idx >> 3;
                int qq  = idx & 7;
                int tr  = (k0 + r) * L + 4 * (g + 1);
                if (tr < 0) tr = 0;
                stg[m] = __ldg((const float4*)(emB + (size_t)tr * 8) + qq);
            }
        }

        int tb = k * L + 4 * g;
        const float* erow = sE[cur] + tid * RS;

        if (g == 0) {
            if (k == 0) {
                float e0[8];
                *(float4*)(e0)     = *((const float4*)erow);
                *(float4*)(e0 + 4) = *((const float4*)erow + 1);
                float s = 0.0f;
#pragma unroll
                for (int j = 0; j < 8; j++) {
                    v[j] = __expf(__ldg(&startt[j]) + e0[j]);
                    s += v[j];
                }
                c = __logf(s);
                float r = __fdividef(1.0f, s);
#pragma unroll
                for (int j = 0; j < 8; j++) v[j] *= r;
            } else {
                float s = v[0]+v[1]+v[2]+v[3]+v[4]+v[5]+v[6]+v[7];
                float r = __fdividef(1.0f, s);
                c = 0.0f;
#pragma unroll
                for (int j = 0; j < 8; j++) v[j] *= r;
            }
        }

        if (g >= 0) {
            int4 tg4 = __ldg((const int4*)(tags + bT + tb));
            int4 mk4 = __ldg((const int4*)(mask + bT + tb));
            int tgA[4] = {tg4.x, tg4.y, tg4.z, tg4.w};
            int mkA[4] = {mk4.x, mk4.y, mk4.z, mk4.w};
#pragma unroll
            for (int q = 0; q < 4; q++) {
                float e[8];
                *(float4*)(e)     = *((const float4*)erow + 2 * q);
                *(float4*)(e + 4) = *((const float4*)erow + 2 * q + 1);
                int tg = tgA[q];
                if (mkA[q] && (tb + q >= 1)) {
                    vstep(v, M2, e);
                    float es = e[0];
#pragma unroll
                    for (int j = 1; j < 8; j++) es = (tg == j) ? e[j] : es;
                    sp += es + __ldg(&trans[pv * 8 + tg]);
                    mcnt++;
                }
                pv = tg;
            }
        } else if (tb >= 0) {   // warm-up (k>0 only)
            int4 mk4 = __ldg((const int4*)(mask + bT + tb));
            int mkA[4] = {mk4.x, mk4.y, mk4.z, mk4.w};
#pragma unroll
            for (int q = 0; q < 4; q++) {
                float e[8];
                *(float4*)(e)     = *((const float4*)erow + 2 * q);
                *(float4*)(e + 4) = *((const float4*)erow + 2 * q + 1);
                if (mkA[q]) vstep(v, M2, e);
            }
        }

        // group-end rescale
        {
            float s = v[0]+v[1]+v[2]+v[3]+v[4]+v[5]+v[6]+v[7];
            float r = __fdividef(1.0f, s);
            c += __logf(s);
#pragma unroll
            for (int j = 0; j < 8; j++) v[j] *= r;
        }

        // store next tile into the alternate buffer, then one sync
        if (more) {
#pragma unroll
            for (int m = 0; m < 8; m++) {
                int idx = m * CPB + tid;
                *((float4*)(sE[cur ^ 1] + (idx >> 3) * RS) + (idx & 7)) = stg[m];
            }
            __syncthreads();
        }
    }

    size_t gidx = (size_t)b * KCH + k;
    g_c  [gidx] = c;
    g_sp [gidx] = sp;
    g_cnt[gidx] = mcnt;
    if (k == KCH - 1) {
#pragma unroll
        for (int j = 0; j < 8; j++) g_nf[b * 8 + j] = v[j];
    }
}

// ---------------------------------------------------------------------------
// Kernel 2: trivial finalize. Block per batch.
// ---------------------------------------------------------------------------
__global__ void __launch_bounds__(256) crf_final(
    const float* __restrict__ em,
    const int* __restrict__ tags,
    const int* __restrict__ mask,
    const float* __restrict__ startt,
    const float* __restrict__ endt,
    float* __restrict__ out,
    int B, int T)
{
    __shared__ float sC[256];
    __shared__ float sS[256];
    __shared__ int   sN[256];

    int b   = blockIdx.x;
    int tid = threadIdx.x;
    size_t bK = (size_t)b * KCH;

    sC[tid] = __ldg(&g_c  [bK + tid]);
    sS[tid] = __ldg(&g_sp [bK + tid]);
    sN[tid] = __ldg(&g_cnt[bK + tid]);
    __syncthreads();

#pragma unroll
    for (int s = 128; s > 0; s >>= 1) {
        if (tid < s) {
            sC[tid] += sC[tid + s];
            sS[tid] += sS[tid + s];
            sN[tid] += sN[tid + s];
        }
        __syncthreads();
    }

    if (tid == 0) {
        size_t bT = (size_t)b * T;
        float vsum = 0.0f;
#pragma unroll
        for (int j = 0; j < 8; j++)
            vsum += g_nf[b * 8 + j] * __expf(__ldg(&endt[j]));
        float logZ = sC[0] + __logf(vsum);

        int cnt = sN[0] + ((__ldg(&mask[bT]) != 0) ? 1 : 0);
        int last_valid = cnt - 1;
        int tag0  = __ldg(&tags[bT]);
        int lastt = __ldg(&tags[bT + last_valid]);
        float score = __ldg(&startt[tag0]) + __ldg(&em[bT * 8 + tag0])
                    + sS[0] + __ldg(&endt[lastt]);
        out[b] = logZ - score;
    }
}

// ---------------------------------------------------------------------------
extern "C" void kernel_launch(void* const* d_in, const int* in_sizes, int n_in,
                              void* d_out, int out_size)
{
    const float* em     = (const float*)d_in[0];
    const int*   tags   = (const int*)d_in[1];
    const int*   mask   = (const int*)d_in[2];
    const float* trans  = (const float*)d_in[3];
    const float* startt = (const float*)d_in[4];
    const float* endt   = (const float*)d_in[5];

    int B = out_size;                 // 256
    int T = in_sizes[0] / (B * 8);    // 16384 (= KCH * L)

    int nblocks = B * (KCH / CPB);    // 512
    crf_chunk_vec<<<nblocks, CPB>>>(em, tags, mask, trans, startt, B, T);

    crf_final<<<B, 256>>>(em, tags, mask, startt, endt, (float*)d_out, B, T);
}